// round 1
// baseline (speedup 1.0000x reference)
#include <cuda_runtime.h>
#include <cstdint>

// DistanceLoss: out[b,n] = min_m ||input[b,n,:] - point[b,m,:]||^2
// B=4, N=8192, M=8192, D=3 (float32).
//
// Strategy: per point precompute (px,py,pz, c=-0.5*|p|^2) in smem.
// Inner loop per (query,point): t = fma(pz,qz, fma(py,qy, fma(px,qx, c)));
// track max(t); final d2 = |q|^2 - 2*max(t), clamped at 0.
// M is split 4 ways across blocks; partials combined via atomicMin on float bits
// (valid: all finals are >= 0 after clamp, so uint bit order == float order).

#define BB      4
#define NQ      8192
#define MP      8192
#define MSPLIT  4
#define MCHUNK  (MP / MSPLIT)   // 2048 points -> 32 KB smem
#define TPB     128             // threads per block = queries per block

__global__ void dl_init_out(float* out, int n) {
    int i = blockIdx.x * blockDim.x + threadIdx.x;
    if (i < n) out[i] = __int_as_float(0x7F800000);  // +inf
}

__global__ __launch_bounds__(TPB)
void dl_nn_kernel(const float* __restrict__ inp,
                  const float* __restrict__ pnt,
                  float* __restrict__ out) {
    __shared__ float4 sp[MCHUNK];

    const int b    = blockIdx.y;
    const int nblk = blockIdx.x / MSPLIT;
    const int mc   = blockIdx.x % MSPLIT;
    const int n    = nblk * TPB + threadIdx.x;

    // Cooperative load of this block's point chunk into smem as (x,y,z,-0.5|p|^2)
    const float* pbase = pnt + ((size_t)b * MP + (size_t)mc * MCHUNK) * 3;
    for (int i = threadIdx.x; i < MCHUNK; i += TPB) {
        float px = pbase[i * 3 + 0];
        float py = pbase[i * 3 + 1];
        float pz = pbase[i * 3 + 2];
        float c  = -0.5f * (px * px + py * py + pz * pz);
        sp[i] = make_float4(px, py, pz, c);
    }
    __syncthreads();

    // Load this thread's query
    const float* q = inp + ((size_t)b * NQ + n) * 3;
    const float qx = q[0], qy = q[1], qz = q[2];
    const float sq = qx * qx + qy * qy + qz * qz;

    const float NEG = -3.402823466e38f;
    float m0 = NEG, m1 = NEG, m2 = NEG, m3 = NEG;
    float m4 = NEG, m5 = NEG, m6 = NEG, m7 = NEG;

    #pragma unroll 4
    for (int j = 0; j < MCHUNK; j += 8) {
        float4 p0 = sp[j + 0];
        float4 p1 = sp[j + 1];
        float4 p2 = sp[j + 2];
        float4 p3 = sp[j + 3];
        float4 p4 = sp[j + 4];
        float4 p5 = sp[j + 5];
        float4 p6 = sp[j + 6];
        float4 p7 = sp[j + 7];

        float t0 = fmaf(p0.z, qz, fmaf(p0.y, qy, fmaf(p0.x, qx, p0.w)));
        float t1 = fmaf(p1.z, qz, fmaf(p1.y, qy, fmaf(p1.x, qx, p1.w)));
        float t2 = fmaf(p2.z, qz, fmaf(p2.y, qy, fmaf(p2.x, qx, p2.w)));
        float t3 = fmaf(p3.z, qz, fmaf(p3.y, qy, fmaf(p3.x, qx, p3.w)));
        float t4 = fmaf(p4.z, qz, fmaf(p4.y, qy, fmaf(p4.x, qx, p4.w)));
        float t5 = fmaf(p5.z, qz, fmaf(p5.y, qy, fmaf(p5.x, qx, p5.w)));
        float t6 = fmaf(p6.z, qz, fmaf(p6.y, qy, fmaf(p6.x, qx, p6.w)));
        float t7 = fmaf(p7.z, qz, fmaf(p7.y, qy, fmaf(p7.x, qx, p7.w)));

        m0 = fmaxf(m0, t0);
        m1 = fmaxf(m1, t1);
        m2 = fmaxf(m2, t2);
        m3 = fmaxf(m3, t3);
        m4 = fmaxf(m4, t4);
        m5 = fmaxf(m5, t5);
        m6 = fmaxf(m6, t6);
        m7 = fmaxf(m7, t7);
    }

    float mv = fmaxf(fmaxf(fmaxf(m0, m1), fmaxf(m2, m3)),
                     fmaxf(fmaxf(m4, m5), fmaxf(m6, m7)));

    // d2 = |q|^2 - 2*max, clamp numerical negatives to 0 (matches reference guard)
    float v = fmaxf(fmaf(-2.0f, mv, sq), 0.0f);

    atomicMin(reinterpret_cast<unsigned int*>(&out[(size_t)b * NQ + n]),
              __float_as_uint(v));
}

extern "C" void kernel_launch(void* const* d_in, const int* in_sizes, int n_in,
                              void* d_out, int out_size) {
    const float* inp = (const float*)d_in[0];   // [B, N, 3]
    const float* pnt = (const float*)d_in[1];   // [B, M, 3]
    float* out = (float*)d_out;                 // [B, N]

    // Init output to +inf (harness poisons it to 0xAA)
    dl_init_out<<<(out_size + 255) / 256, 256>>>(out, out_size);

    dim3 grid((NQ / TPB) * MSPLIT, BB);
    dl_nn_kernel<<<grid, TPB>>>(inp, pnt, out);
}

// round 2
// speedup vs baseline: 1.3018x; 1.3018x over previous
#include <cuda_runtime.h>
#include <cstdint>

// DistanceLoss: out[b,n] = min_m ||input[b,n,:] - point[b,m,:]||^2
// B=4, N=8192, M=8192, D=3 (float32).
//
// R2: packed f32x2 FMA (sm_103a FFMA2) + 4 queries/thread.
//  - Points stored in smem pre-duplicated: point j -> two ulonglong2:
//      sp[2j]   = { (px,px), (py,py) }
//      sp[2j+1] = { (pz,pz), (c,c) }   with c = -0.5*|p|^2
//    so LDS.128 lands directly in aligned register pairs (zero pack MOVs).
//  - Each thread holds 4 queries as two packed pairs (q0,q1), (q2,q3).
//    Per point: 2 LDS.128 + 6 FFMA2 + 4 FMNMX serve 4 (query,point) pairs.
//  - d2 = |q|^2 - 2*max_m(p.q - 0.5|p|^2), clamped at 0.
//  - M split 8 ways across blocks; combine via atomicMin on float bits
//    (valid: results clamped >= 0, so uint order == float order).

#define BB      4
#define NQ      8192
#define MP      8192
#define MSPLIT  8
#define MCHUNK  (MP / MSPLIT)   // 1024 points -> 32 KB smem (duplicated layout)
#define TPB     128
#define QPT     4               // queries per thread
#define QPB     (TPB * QPT)     // 512 queries per block
#define NBLK    (NQ / QPB)      // 16

typedef unsigned long long u64;

__device__ __forceinline__ u64 pack2(float lo, float hi) {
    u64 r;
    asm("mov.b64 %0, {%1, %2};" : "=l"(r) : "f"(lo), "f"(hi));
    return r;
}
__device__ __forceinline__ void unpack2(u64 v, float& lo, float& hi) {
    asm("mov.b64 {%0, %1}, %2;" : "=f"(lo), "=f"(hi) : "l"(v));
}
__device__ __forceinline__ u64 fma2(u64 a, u64 b, u64 c) {
    u64 d;
    asm("fma.rn.f32x2 %0, %1, %2, %3;" : "=l"(d) : "l"(a), "l"(b), "l"(c));
    return d;
}

__global__ void dl_init_out(float* out, int n) {
    int i = blockIdx.x * blockDim.x + threadIdx.x;
    if (i < n) out[i] = __int_as_float(0x7F800000);  // +inf
}

__global__ __launch_bounds__(TPB)
void dl_nn_kernel(const float* __restrict__ inp,
                  const float* __restrict__ pnt,
                  float* __restrict__ out) {
    __shared__ ulonglong2 sp[2 * MCHUNK];   // 32 KB

    const int b    = blockIdx.y;
    const int nblk = blockIdx.x / MSPLIT;
    const int mc   = blockIdx.x % MSPLIT;
    const int t    = threadIdx.x;

    // Fill smem with duplicated point data
    const float* pbase = pnt + ((size_t)b * MP + (size_t)mc * MCHUNK) * 3;
    for (int i = t; i < MCHUNK; i += TPB) {
        float px = pbase[i * 3 + 0];
        float py = pbase[i * 3 + 1];
        float pz = pbase[i * 3 + 2];
        float c  = -0.5f * (px * px + py * py + pz * pz);
        ulonglong2 a, bb2;
        a.x = pack2(px, px);  a.y = pack2(py, py);
        bb2.x = pack2(pz, pz); bb2.y = pack2(c, c);
        sp[2 * i]     = a;
        sp[2 * i + 1] = bb2;
    }
    __syncthreads();

    // Load 4 queries: n_k = nbase + t + k*TPB (coalesced)
    const int nbase = nblk * QPB;
    float qx[QPT], qy[QPT], qz[QPT], sq[QPT];
    #pragma unroll
    for (int k = 0; k < QPT; k++) {
        const float* q = inp + ((size_t)b * NQ + nbase + t + k * TPB) * 3;
        qx[k] = q[0]; qy[k] = q[1]; qz[k] = q[2];
        sq[k] = qx[k] * qx[k] + qy[k] * qy[k] + qz[k] * qz[k];
    }
    const u64 qx01 = pack2(qx[0], qx[1]);
    const u64 qy01 = pack2(qy[0], qy[1]);
    const u64 qz01 = pack2(qz[0], qz[1]);
    const u64 qx23 = pack2(qx[2], qx[3]);
    const u64 qy23 = pack2(qy[2], qy[3]);
    const u64 qz23 = pack2(qz[2], qz[3]);

    const float NEG = -3.402823466e38f;
    float m0 = NEG, m1 = NEG, m2 = NEG, m3 = NEG;

    #pragma unroll 4
    for (int j = 0; j < MCHUNK; j++) {
        ulonglong2 a  = sp[2 * j];       // (px,px),(py,py)
        ulonglong2 bz = sp[2 * j + 1];   // (pz,pz),(c,c)

        u64 t01 = fma2(a.x, qx01, bz.y);
        u64 t23 = fma2(a.x, qx23, bz.y);
        t01 = fma2(a.y, qy01, t01);
        t23 = fma2(a.y, qy23, t23);
        t01 = fma2(bz.x, qz01, t01);
        t23 = fma2(bz.x, qz23, t23);

        float l0, h0, l1, h1;
        unpack2(t01, l0, h0);
        unpack2(t23, l1, h1);
        m0 = fmaxf(m0, l0);
        m1 = fmaxf(m1, h0);
        m2 = fmaxf(m2, l1);
        m3 = fmaxf(m3, h1);
    }

    float mv[QPT] = {m0, m1, m2, m3};
    #pragma unroll
    for (int k = 0; k < QPT; k++) {
        float v = fmaxf(fmaf(-2.0f, mv[k], sq[k]), 0.0f);
        atomicMin(reinterpret_cast<unsigned int*>(
                      &out[(size_t)b * NQ + nbase + t + k * TPB]),
                  __float_as_uint(v));
    }
}

extern "C" void kernel_launch(void* const* d_in, const int* in_sizes, int n_in,
                              void* d_out, int out_size) {
    const float* inp = (const float*)d_in[0];   // [B, N, 3]
    const float* pnt = (const float*)d_in[1];   // [B, M, 3]
    float* out = (float*)d_out;                 // [B, N]

    dl_init_out<<<(out_size + 255) / 256, 256>>>(out, out_size);

    dim3 grid(NBLK * MSPLIT, BB);
    dl_nn_kernel<<<grid, TPB>>>(inp, pnt, out);
}

// round 3
// speedup vs baseline: 1.4239x; 1.0939x over previous
#include <cuda_runtime.h>
#include <cstdint>

// DistanceLoss: out[b,n] = min_m ||input[b,n,:] - point[b,m,:]||^2
// B=4, N=8192, M=8192, D=3 (float32).
//
// R3: 8 queries/thread (FFMA2-packed as 4 pairs) + 32-way M split for occupancy.
//  - Points in smem pre-duplicated: point j -> two ulonglong2:
//      sp[2j]   = { (px,px), (py,py) }
//      sp[2j+1] = { (pz,pz), (c,c) },  c = -0.5*|p|^2
//  - Per point: 2 LDS.128 + 12 FFMA2 + 8 FMNMX serve 8 (query,point) pairs.
//  - d2 = |q|^2 - 2*max_m(p.q - 0.5|p|^2), clamped at 0.
//  - Partials combined via atomicMin on float bits (valid: results >= 0).

#define BB      4
#define NQ      8192
#define MP      8192
#define MSPLIT  32
#define MCHUNK  (MP / MSPLIT)   // 256 points -> 8 KB smem (duplicated layout)
#define TPB     128
#define QPT     8               // queries per thread
#define QPB     (TPB * QPT)     // 1024 queries per block
#define NBLK    (NQ / QPB)      // 8

typedef unsigned long long u64;

__device__ __forceinline__ u64 pack2(float lo, float hi) {
    u64 r;
    asm("mov.b64 %0, {%1, %2};" : "=l"(r) : "f"(lo), "f"(hi));
    return r;
}
__device__ __forceinline__ void unpack2(u64 v, float& lo, float& hi) {
    asm("mov.b64 {%0, %1}, %2;" : "=f"(lo), "=f"(hi) : "l"(v));
}
__device__ __forceinline__ u64 fma2(u64 a, u64 b, u64 c) {
    u64 d;
    asm("fma.rn.f32x2 %0, %1, %2, %3;" : "=l"(d) : "l"(a), "l"(b), "l"(c));
    return d;
}

__global__ void dl_init_out(float* out, int n) {
    int i = blockIdx.x * blockDim.x + threadIdx.x;
    if (i < n) out[i] = __int_as_float(0x7F800000);  // +inf
}

__global__ __launch_bounds__(TPB)
void dl_nn_kernel(const float* __restrict__ inp,
                  const float* __restrict__ pnt,
                  float* __restrict__ out) {
    __shared__ ulonglong2 sp[2 * MCHUNK];   // 8 KB

    const int b    = blockIdx.y;
    const int nblk = blockIdx.x / MSPLIT;
    const int mc   = blockIdx.x % MSPLIT;
    const int t    = threadIdx.x;

    // Fill smem with duplicated point data
    const float* pbase = pnt + ((size_t)b * MP + (size_t)mc * MCHUNK) * 3;
    for (int i = t; i < MCHUNK; i += TPB) {
        float px = pbase[i * 3 + 0];
        float py = pbase[i * 3 + 1];
        float pz = pbase[i * 3 + 2];
        float c  = -0.5f * (px * px + py * py + pz * pz);
        ulonglong2 a, bb2;
        a.x = pack2(px, px);  a.y = pack2(py, py);
        bb2.x = pack2(pz, pz); bb2.y = pack2(c, c);
        sp[2 * i]     = a;
        sp[2 * i + 1] = bb2;
    }
    __syncthreads();

    // Load 8 queries: n_k = nbase + t + k*TPB (coalesced per k)
    const int nbase = nblk * QPB;
    float qx[QPT], qy[QPT], qz[QPT], sq[QPT];
    #pragma unroll
    for (int k = 0; k < QPT; k++) {
        const float* q = inp + ((size_t)b * NQ + nbase + t + k * TPB) * 3;
        qx[k] = q[0]; qy[k] = q[1]; qz[k] = q[2];
        sq[k] = qx[k] * qx[k] + qy[k] * qy[k] + qz[k] * qz[k];
    }
    u64 Qx[4], Qy[4], Qz[4];
    #pragma unroll
    for (int p = 0; p < 4; p++) {
        Qx[p] = pack2(qx[2 * p], qx[2 * p + 1]);
        Qy[p] = pack2(qy[2 * p], qy[2 * p + 1]);
        Qz[p] = pack2(qz[2 * p], qz[2 * p + 1]);
    }

    const float NEG = -3.402823466e38f;
    float m[QPT];
    #pragma unroll
    for (int k = 0; k < QPT; k++) m[k] = NEG;

    #pragma unroll 4
    for (int j = 0; j < MCHUNK; j++) {
        ulonglong2 a  = sp[2 * j];       // (px,px),(py,py)
        ulonglong2 bz = sp[2 * j + 1];   // (pz,pz),(c,c)

        u64 tt[4];
        #pragma unroll
        for (int p = 0; p < 4; p++) tt[p] = fma2(a.x, Qx[p], bz.y);
        #pragma unroll
        for (int p = 0; p < 4; p++) tt[p] = fma2(a.y, Qy[p], tt[p]);
        #pragma unroll
        for (int p = 0; p < 4; p++) tt[p] = fma2(bz.x, Qz[p], tt[p]);

        #pragma unroll
        for (int p = 0; p < 4; p++) {
            float lo, hi;
            unpack2(tt[p], lo, hi);
            m[2 * p]     = fmaxf(m[2 * p], lo);
            m[2 * p + 1] = fmaxf(m[2 * p + 1], hi);
        }
    }

    #pragma unroll
    for (int k = 0; k < QPT; k++) {
        float v = fmaxf(fmaf(-2.0f, m[k], sq[k]), 0.0f);
        atomicMin(reinterpret_cast<unsigned int*>(
                      &out[(size_t)b * NQ + nbase + t + k * TPB]),
                  __float_as_uint(v));
    }
}

extern "C" void kernel_launch(void* const* d_in, const int* in_sizes, int n_in,
                              void* d_out, int out_size) {
    const float* inp = (const float*)d_in[0];   // [B, N, 3]
    const float* pnt = (const float*)d_in[1];   // [B, M, 3]
    float* out = (float*)d_out;                 // [B, N]

    dl_init_out<<<(out_size + 255) / 256, 256>>>(out, out_size);

    dim3 grid(NBLK * MSPLIT, BB);
    dl_nn_kernel<<<grid, TPB>>>(inp, pnt, out);
}

// round 5
// speedup vs baseline: 1.7872x; 1.2551x over previous
#include <cuda_runtime.h>
#include <cstdint>

// DistanceLoss: out[b,n] = min_m ||input[b,n,:] - point[b,m,:]||^2
// B=4, N=8192, M=8192, D=3 (float32).
//
// R4: point-PAIR packed smem (no duplication -> half the crossbar bytes),
//     queries duplicated in registers, FFMA2 computes one query vs two points.
//  smem per 2-point group g:
//    sp[2g]   = { (p0x,p1x), (p0y,p1y) }
//    sp[2g+1] = { (p0z,p1z), (c0,c1) },  c = -0.5*|p|^2
//  Per group per warp: 2 LDS.128 + 24 FFMA2 + 16 FMNMX serve 512 pairs.
//  d2 = |q|^2 - 2*max_m(p.q - 0.5|p|^2), clamped at 0.
//  M split into 23 chunks (~358 points, even sizes) -> 736 blocks ~= 148*5,
//  near-uniform single wave at 5 blocks/SM. Partials merged via atomicMin
//  on float bits (valid: results clamped >= 0).

#define BB      4
#define NQ      8192
#define MP      8192
#define MSPLIT  23
#define MCH     358              // base chunk size (even); last chunk = 316
#define MAXGRP  (MCH / 2)        // 179 groups -> 5728 B smem
#define TPB     128
#define QPT     8                // queries per thread
#define QPB     (TPB * QPT)      // 1024 queries per block
#define NBLK    (NQ / QPB)       // 8

typedef unsigned long long u64;

__device__ __forceinline__ u64 pack2(float lo, float hi) {
    u64 r;
    asm("mov.b64 %0, {%1, %2};" : "=l"(r) : "f"(lo), "f"(hi));
    return r;
}
__device__ __forceinline__ void unpack2(u64 v, float& lo, float& hi) {
    asm("mov.b64 {%0, %1}, %2;" : "=f"(lo), "=f"(hi) : "l"(v));
}
__device__ __forceinline__ u64 fma2(u64 a, u64 b, u64 c) {
    u64 d;
    asm("fma.rn.f32x2 %0, %1, %2, %3;" : "=l"(d) : "l"(a), "l"(b), "l"(c));
    return d;
}

__global__ void dl_init_out(float* out, int n) {
    int i = blockIdx.x * blockDim.x + threadIdx.x;
    if (i < n) out[i] = __int_as_float(0x7F800000);  // +inf
}

__global__ __launch_bounds__(TPB, 5)
void dl_nn_kernel(const float* __restrict__ inp,
                  const float* __restrict__ pnt,
                  float* __restrict__ out) {
    __shared__ ulonglong2 sp[2 * MAXGRP];

    const int b    = blockIdx.y;
    const int nblk = blockIdx.x / MSPLIT;
    const int mc   = blockIdx.x % MSPLIT;
    const int t    = threadIdx.x;

    // This chunk's point range [m0, m1), both even-sized.
    const int m0 = mc * MCH;
    int m1 = m0 + MCH;
    if (m1 > MP) m1 = MP;
    const int ngrp = (m1 - m0) >> 1;

    // Fill smem: group i = points (m0+2i, m0+2i+1), pair-packed.
    const float* pbase = pnt + ((size_t)b * MP + m0) * 3;
    for (int i = t; i < ngrp; i += TPB) {
        const float* p0 = pbase + 6 * i;
        float p0x = p0[0], p0y = p0[1], p0z = p0[2];
        float p1x = p0[3], p1y = p0[4], p1z = p0[5];
        float c0 = -0.5f * (p0x * p0x + p0y * p0y + p0z * p0z);
        float c1 = -0.5f * (p1x * p1x + p1y * p1y + p1z * p1z);
        ulonglong2 a, bb2;
        a.x  = pack2(p0x, p1x);  a.y  = pack2(p0y, p1y);
        bb2.x = pack2(p0z, p1z); bb2.y = pack2(c0, c1);
        sp[2 * i]     = a;
        sp[2 * i + 1] = bb2;
    }
    __syncthreads();

    // Load 8 queries (coalesced per k), duplicate into packed pairs (qk,qk).
    const int nbase = nblk * QPB;
    u64 Qx[QPT], Qy[QPT], Qz[QPT];
    #pragma unroll
    for (int k = 0; k < QPT; k++) {
        const float* q = inp + ((size_t)b * NQ + nbase + t + k * TPB) * 3;
        float qx = q[0], qy = q[1], qz = q[2];
        Qx[k] = pack2(qx, qx);
        Qy[k] = pack2(qy, qy);
        Qz[k] = pack2(qz, qz);
    }

    const float NEG = -3.402823466e38f;
    float m[QPT];
    #pragma unroll
    for (int k = 0; k < QPT; k++) m[k] = NEG;

    #pragma unroll 2
    for (int g = 0; g < ngrp; g++) {
        ulonglong2 a  = sp[2 * g];       // (p0x,p1x),(p0y,p1y)
        ulonglong2 bz = sp[2 * g + 1];   // (p0z,p1z),(c0,c1)

        u64 tt[QPT];
        #pragma unroll
        for (int k = 0; k < QPT; k++) tt[k] = fma2(a.x, Qx[k], bz.y);
        #pragma unroll
        for (int k = 0; k < QPT; k++) tt[k] = fma2(a.y, Qy[k], tt[k]);
        #pragma unroll
        for (int k = 0; k < QPT; k++) tt[k] = fma2(bz.x, Qz[k], tt[k]);

        #pragma unroll
        for (int k = 0; k < QPT; k++) {
            float lo, hi;
            unpack2(tt[k], lo, hi);
            m[k] = fmaxf(m[k], fmaxf(lo, hi));
        }
    }

    #pragma unroll
    for (int k = 0; k < QPT; k++) {
        float qx, qy, qz, dummy;
        unpack2(Qx[k], qx, dummy);
        unpack2(Qy[k], qy, dummy);
        unpack2(Qz[k], qz, dummy);
        float sq = qx * qx + qy * qy + qz * qz;
        float v = fmaxf(fmaf(-2.0f, m[k], sq), 0.0f);
        atomicMin(reinterpret_cast<unsigned int*>(
                      &out[(size_t)b * NQ + nbase + t + k * TPB]),
                  __float_as_uint(v));
    }
}

extern "C" void kernel_launch(void* const* d_in, const int* in_sizes, int n_in,
                              void* d_out, int out_size) {
    const float* inp = (const float*)d_in[0];   // [B, N, 3]
    const float* pnt = (const float*)d_in[1];   // [B, M, 3]
    float* out = (float*)d_out;                 // [B, N]

    dl_init_out<<<(out_size + 255) / 256, 256>>>(out, out_size);

    dim3 grid(NBLK * MSPLIT, BB);
    dl_nn_kernel<<<grid, TPB>>>(inp, pnt, out);
}